// round 9
// baseline (speedup 1.0000x reference)
#include <cuda_runtime.h>
#include <cuda_fp16.h>

// Problem constants
constexpr int Bb  = 2;
constexpr int Ll  = 2048;
constexpr int Hh  = 1024;
constexpr int NHh = 16;
constexpr int DHd = 64;

constexpr int GM = Bb * Ll;   // 4096
constexpr int GN = Hh;        // 1024
constexpr int GK = Hh;        // 1024

// ---------------- device scratch ----------------
__device__ __half g_qh[GM * Hh];
__device__ __half g_kh[GM * Hh];
__device__ __half g_vh[GM * Hh];
__device__ __half g_Wqh[Hh * Hh];
__device__ __half g_Wkh[Hh * Hh];
__device__ __half g_Wvh[Hh * Hh];
__device__ __half g_Wmh[Hh * Hh];
__device__ __half g_qp[GM * Hh];
__device__ __half g_kp[GM * Hh];
__device__ __half g_vp[GM * Hh];
__device__ __half g_atted[GM * Hh];
__device__ float  g_thr[GM];
__device__ float  g_colsum[GM];

// ---------------- helpers ----------------
__device__ __forceinline__ unsigned f22h(float a, float b) {
    __half2 h = __floats2half2_rn(a, b);
    return *(unsigned*)&h;
}

__device__ __forceinline__ unsigned smem_u32(const void* p) {
    unsigned a;
    asm("{ .reg .u64 t; cvta.to.shared.u64 t, %1; cvt.u32.u64 %0, t; }" : "=r"(a) : "l"(p));
    return a;
}

__device__ __forceinline__ void cp16(unsigned dst, const void* src) {
    asm volatile("cp.async.cg.shared.global [%0], [%1], 16;" :: "r"(dst), "l"(src));
}
#define CP_COMMIT() asm volatile("cp.async.commit_group;")
#define CP_WAIT(n)  asm volatile("cp.async.wait_group %0;" :: "n"(n))

__device__ __forceinline__ void ldsm_x4(unsigned& r0, unsigned& r1, unsigned& r2, unsigned& r3, unsigned addr) {
    asm volatile("ldmatrix.sync.aligned.m8n8.x4.shared.b16 {%0,%1,%2,%3}, [%4];"
                 : "=r"(r0), "=r"(r1), "=r"(r2), "=r"(r3) : "r"(addr));
}
__device__ __forceinline__ void ldsm_x4t(unsigned& r0, unsigned& r1, unsigned& r2, unsigned& r3, unsigned addr) {
    asm volatile("ldmatrix.sync.aligned.m8n8.x4.trans.shared.b16 {%0,%1,%2,%3}, [%4];"
                 : "=r"(r0), "=r"(r1), "=r"(r2), "=r"(r3) : "r"(addr));
}

__device__ __forceinline__ void mma_f16(
    float& c0, float& c1, float& c2, float& c3,
    unsigned a0, unsigned a1, unsigned a2, unsigned a3,
    unsigned b0, unsigned b1)
{
    asm volatile(
        "mma.sync.aligned.m16n8k16.row.col.f32.f16.f16.f32 "
        "{%0,%1,%2,%3},{%4,%5,%6,%7},{%8,%9},{%0,%1,%2,%3};"
        : "+f"(c0), "+f"(c1), "+f"(c2), "+f"(c3)
        : "r"(a0), "r"(a1), "r"(a2), "r"(a3), "r"(b0), "r"(b1));
}

__device__ __forceinline__ unsigned f2key(float f) {
    unsigned b = __float_as_uint(f);
    return (b & 0x80000000u) ? ~b : (b | 0x80000000u);
}
__device__ __forceinline__ float key2f(unsigned u) {
    return __uint_as_float((u & 0x80000000u) ? (u & 0x7fffffffu) : ~u);
}

// ---------------- converter: fp32 -> fp16 for all GEMM operands ----------------
__global__ void __launch_bounds__(256) cvt_all(
    const float* __restrict__ Wq, const float* __restrict__ Wk,
    const float* __restrict__ Wv, const float* __restrict__ Wm,
    const float* __restrict__ q,  const float* __restrict__ k,
    const float* __restrict__ v,
    __half* Wqh, __half* Wkh, __half* Wvh, __half* Wmh,
    __half* qh, __half* kh, __half* vh)
{
    int bid = blockIdx.x;
    const float* src; __half* dst; int off;
    if      (bid < 512)  { src = Wq; dst = Wqh; off = bid; }
    else if (bid < 1024) { src = Wk; dst = Wkh; off = bid - 512; }
    else if (bid < 1536) { src = Wv; dst = Wvh; off = bid - 1024; }
    else if (bid < 2048) { src = Wm; dst = Wmh; off = bid - 1536; }
    else if (bid < 4096) { src = q;  dst = qh;  off = bid - 2048; }
    else if (bid < 6144) { src = k;  dst = kh;  off = bid - 4096; }
    else                 { src = v;  dst = vh;  off = bid - 6144; }
    size_t base = (size_t)off * 2048 + threadIdx.x * 8;
    float4 f0 = *(const float4*)&src[base];
    float4 f1 = *(const float4*)&src[base + 4];
    uint4 o = { f22h(f0.x, f0.y), f22h(f0.z, f0.w), f22h(f1.x, f1.y), f22h(f1.z, f1.w) };
    *(uint4*)&dst[base] = o;
}

// ---------------- fp16 GEMM v3 (unchanged from R8 winner) ----------------
constexpr int G_ASTH = 40;
constexpr int G_BSTH = 136;
constexpr int G_ASB  = 128 * G_ASTH * 2;
constexpr int G_BSB  = 32 * G_BSTH * 2;
constexpr int G_STAGE = G_ASB + G_BSB;
constexpr int GEMM_SMEM = 3 * G_STAGE;

template <typename TC, bool GATED>
__global__ void __launch_bounds__(512, 2) gemm_f16_kernel(
    const __half* __restrict__ A0, const __half* __restrict__ A1, const __half* __restrict__ A2,
    const __half* __restrict__ W0, const __half* __restrict__ W1, const __half* __restrict__ W2,
    const float* __restrict__ b0p, const float* __restrict__ b1p, const float* __restrict__ b2p,
    TC* __restrict__ C0, TC* __restrict__ C1, TC* __restrict__ C2,
    const float* __restrict__ colsum, const float* __restrict__ thr)
{
    extern __shared__ __align__(16) char smb[];
    const unsigned sb = smem_u32(smb);

    const int z = blockIdx.z;
    const __half* A = (z == 0) ? A0 : (z == 1) ? A1 : A2;
    const __half* W = (z == 0) ? W0 : (z == 1) ? W1 : W2;
    const float* bias = (z == 0) ? b0p : (z == 1) ? b1p : b2p;
    TC* C = (z == 0) ? C0 : (z == 1) ? C1 : C2;

    const int t    = threadIdx.x;
    const int w    = t >> 5;
    const int lane = t & 31;
    const int g    = lane >> 2;
    const int tg   = lane & 3;
    const int wm   = (w & 3) * 32;
    const int wn   = (w >> 2) * 32;

    const int m0 = blockIdx.y * 128;
    const int n0 = blockIdx.x * 128;

    const int arow = (lane & 7) + ((lane >> 3) & 1) * 8;
    const int acol = (lane >> 4) * 8;

    const int a_row = t >> 2;
    const int a_seg = (t & 3) * 8;
    const int w_row = t >> 4;
    const int w_seg = (t & 15) * 8;

    auto stage = [&](int s, int kt) {
        const int k0 = kt * 32;
        unsigned as = sb + s * G_STAGE;
        unsigned bs = as + G_ASB;
        cp16(as + (a_row * G_ASTH + a_seg) * 2, &A[(size_t)(m0 + a_row) * GK + k0 + a_seg]);
        cp16(bs + (w_row * G_BSTH + w_seg) * 2, &W[(size_t)(k0 + w_row) * GN + n0 + w_seg]);
    };

    constexpr int NT = GK / 32;
    stage(0, 0); CP_COMMIT();
    stage(1, 1); CP_COMMIT();

    float c[2][4][4] = {};

    for (int kt = 0; kt < NT; kt++) {
        CP_WAIT(1);
        __syncthreads();
        if (kt + 2 < NT) stage((kt + 2) % 3, kt + 2);
        CP_COMMIT();

        const unsigned as = sb + (kt % 3) * G_STAGE;
        const unsigned bs = as + G_ASB;

        #pragma unroll
        for (int kb = 0; kb < 2; kb++) {
            unsigned a[2][4];
            #pragma unroll
            for (int mt = 0; mt < 2; mt++)
                ldsm_x4(a[mt][0], a[mt][1], a[mt][2], a[mt][3],
                        as + ((wm + mt * 16 + arow) * G_ASTH + kb * 16 + acol) * 2);
            unsigned bf[2][4];
            #pragma unroll
            for (int nn = 0; nn < 2; nn++)
                ldsm_x4t(bf[nn][0], bf[nn][1], bf[nn][2], bf[nn][3],
                         bs + ((kb * 16 + arow) * G_BSTH + wn + nn * 16 + acol) * 2);
            #pragma unroll
            for (int mt = 0; mt < 2; mt++)
                #pragma unroll
                for (int ng = 0; ng < 4; ng++)
                    mma_f16(c[mt][ng][0], c[mt][ng][1], c[mt][ng][2], c[mt][ng][3],
                            a[mt][0], a[mt][1], a[mt][2], a[mt][3],
                            bf[ng >> 1][(ng & 1) * 2], bf[ng >> 1][(ng & 1) * 2 + 1]);
        }
        __syncthreads();
    }

    #pragma unroll
    for (int mt = 0; mt < 2; mt++) {
        const int r = m0 + wm + mt * 16 + g;
        float gv0 = 1.f, gv1 = 1.f;
        if (GATED) {
            gv0 = ((colsum[r]     - thr[r])     > 0.f) ? 1.f : 0.f;
            gv1 = ((colsum[r + 8] - thr[r + 8]) > 0.f) ? 1.f : 0.f;
        }
        #pragma unroll
        for (int ng = 0; ng < 4; ng++) {
            const int col = n0 + wn + ng * 8 + 2 * tg;
            float2 bb = *(const float2*)&bias[col];
            float o00 = c[mt][ng][0] * gv0 + bb.x;
            float o01 = c[mt][ng][1] * gv0 + bb.y;
            float o10 = c[mt][ng][2] * gv1 + bb.x;
            float o11 = c[mt][ng][3] * gv1 + bb.y;
            if constexpr (sizeof(TC) == 2) {
                *(unsigned*)&C[(size_t)r * GN + col]       = f22h(o00, o01);
                *(unsigned*)&C[(size_t)(r + 8) * GN + col] = f22h(o10, o11);
            } else {
                *(float2*)&C[(size_t)r * GN + col]       = make_float2(o00, o01);
                *(float2*)&C[(size_t)(r + 8) * GN + col] = make_float2(o10, o11);
            }
        }
    }
}

// ---------------- threshold (also zeroes colsum) ----------------
__global__ void __launch_bounds__(128) threshold_kernel(
    const __half* __restrict__ qp, const __half* __restrict__ kp,
    const float* __restrict__ Wt, const float* __restrict__ bt,
    float* __restrict__ thr, float* __restrict__ colsum)
{
    __shared__ float red[4];
    const int row = blockIdx.x;
    const int t = threadIdx.x;
    const __half* qr = qp + (size_t)row * Hh;
    const __half* kr = kp + (size_t)row * Hh;
    float acc = 0.f;
    for (int i = t; i < Hh; i += 128)
        acc += __half2float(qr[i]) * __half2float(kr[i]) * Wt[i];
    #pragma unroll
    for (int o = 16; o; o >>= 1) acc += __shfl_xor_sync(0xffffffffu, acc, o);
    if ((t & 31) == 0) red[t >> 5] = acc;
    __syncthreads();
    if (t == 0) {
        thr[row] = red[0] + red[1] + red[2] + red[3] + bt[0];
        colsum[row] = 0.f;
    }
}

// ---------------- attention: QT=16, 512 thr, 2 blocks/SM, 2-stage KV ----------------
constexpr int QT  = 16;
constexpr int KT  = 128;
constexpr int NKT = Ll / KT;        // 16

constexpr int SSTH  = 2056;
constexpr int QSTH  = 72;
constexpr int KVSTH = 72;
constexpr int KVBUF = KT * KVSTH;   // 9216 halves / stage

constexpr int QH_OFF = QT * SSTH;                // 32896 halves
constexpr int KV_OFF = QH_OFF + QT * QSTH;       // 34048
constexpr int FL_OFF = KV_OFF + 2 * KVBUF;       // 52480 halves -> 104960 B
constexpr int ATTN_SMEM = FL_OFF * 2 + 192;      // ~105 KB -> 2 blocks/SM

constexpr int RROW  = 68;
constexpr int RSLAB = QT * RROW;    // 1088 floats per slab

__global__ void __launch_bounds__(512, 2) attn_kernel(
    const __half* __restrict__ qp, const __half* __restrict__ kp,
    const __half* __restrict__ vp, const unsigned char* __restrict__ mask,
    __half* __restrict__ atted, float* __restrict__ colsum)
{
    extern __shared__ __align__(16) char smb[];
    __half* Sh = (__half*)smb;
    __half* Qh = (__half*)smb + QH_OFF;
    unsigned* rowmaxU = (unsigned*)(smb + FL_OFF * 2);
    float* invl = (float*)(smb + FL_OFF * 2 + 64);
    const unsigned sb   = smem_u32(smb);
    const unsigned shS  = sb;
    const unsigned shQ  = sb + QH_OFF * 2;
    const unsigned shKV = sb + KV_OFF * 2;

    const int t    = threadIdx.x;
    const int w    = t >> 5;
    const int lane = t & 31;
    const int g    = lane >> 2;
    const int tg   = lane & 3;

    const int bx = blockIdx.x;
    const int qt = bx & 127;
    const int h  = (bx >> 7) & 15;
    const int b  = bx >> 11;
    const int q0 = qt * QT;
    const int hd = h * DHd;

    const int arow = (lane & 7) + ((lane >> 3) & 1) * 8;
    const int acol = (lane >> 4) * 8;
    const int brow = lane & 7;
    const int bseg = (lane >> 3) * 8;

    const __half* kbase = kp + (size_t)(b * Ll) * Hh + hd;
    const __half* vbase = vp + (size_t)(b * Ll) * Hh + hd;

    const int s_row0 = t >> 3;          // 0..63 (+64)
    const int s_c8   = (t & 7) * 8;

    auto stage_tile = [&](int s, const __half* base, int tile) {
        const __half* src = base + (size_t)(tile * KT) * Hh;
        unsigned dst = shKV + s * (KVBUF * 2);
        cp16(dst + (s_row0 * KVSTH + s_c8) * 2,        &src[(size_t)s_row0 * Hh + s_c8]);
        cp16(dst + ((s_row0 + 64) * KVSTH + s_c8) * 2, &src[(size_t)(s_row0 + 64) * Hh + s_c8]);
    };

    // ---- init rowmax, stage Q, prologue K tiles ----
    if (t < 16) rowmaxU[t] = 0u;
    if (t < 128) {
        int r = t >> 3, c8 = (t & 7) * 8;
        *(uint4*)&Qh[r * QSTH + c8] =
            *(const uint4*)&qp[(size_t)(b * Ll + q0 + r) * Hh + hd + c8];
    }
    stage_tile(0, kbase, 0); CP_COMMIT();
    stage_tile(1, kbase, 1); CP_COMMIT();
    __syncthreads();

    // ---- Q fragments: aq[kb][4], kb = 4 k-steps of 16 ----
    unsigned aq[4][4];
    #pragma unroll
    for (int kb = 0; kb < 4; kb++)
        ldsm_x4(aq[kb][0], aq[kb][1], aq[kb][2], aq[kb][3],
                shQ + (arow * QSTH + kb * 16 + acol) * 2);

    const int n0 = w * 8;               // warp key-slice of 8

    // ---- QK: S = Q K^T / 8, running row max ----
    float lm0 = -1e30f, lm1 = -1e30f;

    for (int kt = 0; kt < NKT; kt++) {
        CP_WAIT(1);
        __syncthreads();

        const unsigned kvb = shKV + (kt & 1) * (KVBUF * 2);
        unsigned bk[4][2];
        {
            unsigned r0, r1, r2, r3;
            ldsm_x4(r0, r1, r2, r3, kvb + ((n0 + brow) * KVSTH + bseg) * 2);
            bk[0][0] = r0; bk[0][1] = r1; bk[1][0] = r2; bk[1][1] = r3;
            ldsm_x4(r0, r1, r2, r3, kvb + ((n0 + brow) * KVSTH + 32 + bseg) * 2);
            bk[2][0] = r0; bk[2][1] = r1; bk[3][0] = r2; bk[3][1] = r3;
        }

        float c0 = 0.f, c1 = 0.f, c2 = 0.f, c3 = 0.f;
        #pragma unroll
        for (int kb = 0; kb < 4; kb++)
            mma_f16(c0, c1, c2, c3,
                    aq[kb][0], aq[kb][1], aq[kb][2], aq[kb][3],
                    bk[kb][0], bk[kb][1]);

        const int key = kt * KT + n0 + 2 * tg;
        const unsigned char m0 = mask[b * Ll + key];
        const unsigned char m1 = mask[b * Ll + key + 1];
        float s00 = m0 ? -1e9f : c0 * 0.125f;
        float s01 = m1 ? -1e9f : c1 * 0.125f;
        float s10 = m0 ? -1e9f : c2 * 0.125f;
        float s11 = m1 ? -1e9f : c3 * 0.125f;
        lm0 = fmaxf(lm0, fmaxf(s00, s01));
        lm1 = fmaxf(lm1, fmaxf(s10, s11));
        *(unsigned*)&Sh[g * SSTH + key]       = f22h(s00, s01);
        *(unsigned*)&Sh[(g + 8) * SSTH + key] = f22h(s10, s11);

        __syncthreads();                 // all reads of buf kt&1 done
        if (kt + 2 < NKT) stage_tile(kt & 1, kbase, kt + 2);
        CP_COMMIT();
    }

    // ---- row max reduce ----
    lm0 = fmaxf(lm0, __shfl_xor_sync(0xffffffffu, lm0, 1));
    lm0 = fmaxf(lm0, __shfl_xor_sync(0xffffffffu, lm0, 2));
    lm1 = fmaxf(lm1, __shfl_xor_sync(0xffffffffu, lm1, 1));
    lm1 = fmaxf(lm1, __shfl_xor_sync(0xffffffffu, lm1, 2));
    if (tg == 0) {
        atomicMax(&rowmaxU[g],     f2key(lm0));
        atomicMax(&rowmaxU[g + 8], f2key(lm1));
    }
    __syncthreads();

    // prologue V tiles (overlap with exp/colsum)
    stage_tile(0, vbase, 0); CP_COMMIT();
    stage_tile(1, vbase, 1); CP_COMMIT();

    // ---- exp in place (half), row sums: warp w owns row w (w<16) ----
    if (w < 16) {
        const float m = key2f(rowmaxU[w]);
        __half* Sr = Sh + w * SSTH;
        float sum = 0.f;
        #pragma unroll 4
        for (int i = 0; i < 32; i++) {
            const int cc = i * 64 + 2 * lane;
            __half2 hv = *(__half2*)&Sr[cc];
            float e0 = __expf(__half2float(hv.x) - m);
            float e1 = __expf(__half2float(hv.y) - m);
            sum += e0 + e1;
            *(unsigned*)&Sr[cc] = f22h(e0, e1);
        }
        #pragma unroll
        for (int o = 16; o; o >>= 1) sum += __shfl_xor_sync(0xffffffffu, sum, o);
        if (lane == 0) invl[w] = 1.f / sum;
    }
    __syncthreads();

    // ---- colsum ----
    {
        float il[QT];
        #pragma unroll
        for (int r = 0; r < QT; r++) il[r] = invl[r];
        for (int k2 = 2 * t; k2 < Ll; k2 += 1024) {
            float a0 = 0.f, a1 = 0.f;
            #pragma unroll
            for (int r = 0; r < QT; r++) {
                __half2 p = *(__half2*)&Sh[r * SSTH + k2];
                a0 += __half2float(p.x) * il[r];
                a1 += __half2float(p.y) * il[r];
            }
            atomicAdd(&colsum[b * Ll + k2],     a0);
            atomicAdd(&colsum[b * Ll + k2 + 1], a1);
        }
    }

    // ---- PV: warp = key-slice (w&7)*16 x d-half (w>>3)*32 ----
    const int sk = (w & 7) * 16;
    const int dh = (w >> 3) * 32;
    float c[4][4] = {};

    for (int vt = 0; vt < NKT; vt++) {
        CP_WAIT(1);
        __syncthreads();

        const unsigned kvb = shKV + (vt & 1) * (KVBUF * 2);

        unsigned ap[4];
        ldsm_x4(ap[0], ap[1], ap[2], ap[3],
                shS + (arow * SSTH + vt * KT + sk + acol) * 2);

        unsigned bv[2][4];
        #pragma unroll
        for (int nn = 0; nn < 2; nn++)
            ldsm_x4t(bv[nn][0], bv[nn][1], bv[nn][2], bv[nn][3],
                     kvb + ((sk + arow) * KVSTH + dh + nn * 16 + acol) * 2);

        #pragma unroll
        for (int ng = 0; ng < 4; ng++)
            mma_f16(c[ng][0], c[ng][1], c[ng][2], c[ng][3],
                    ap[0], ap[1], ap[2], ap[3],
                    bv[ng >> 1][(ng & 1) * 2], bv[ng >> 1][(ng & 1) * 2 + 1]);

        __syncthreads();                 // all reads of buf vt&1 done
        if (vt + 2 < NKT) stage_tile(vt & 1, vbase, vt + 2);
        CP_COMMIT();
    }

    // ---- 8-way reduction of key-slice partials (fp32 slabs over S region) ----
    float* R = (float*)smb;
    const int slab = w & 7;
    #pragma unroll
    for (int ng = 0; ng < 4; ng++) {
        const int col = dh + ng * 8 + 2 * tg;
        *(float2*)&R[slab * RSLAB + g * RROW + col]       = make_float2(c[ng][0], c[ng][1]);
        *(float2*)&R[slab * RSLAB + (g + 8) * RROW + col] = make_float2(c[ng][2], c[ng][3]);
    }
    __syncthreads();

    for (int id = t; id < QT * DHd / 2; id += 512) {
        const int r = id >> 5;
        const int d = (id & 31) * 2;
        float s0 = 0.f, s1 = 0.f;
        #pragma unroll
        for (int sl = 0; sl < 8; sl++) {
            s0 += R[sl * RSLAB + r * RROW + d];
            s1 += R[sl * RSLAB + r * RROW + d + 1];
        }
        const float il = invl[r];
        *(unsigned*)&atted[(size_t)(b * Ll + q0 + r) * Hh + hd + d] = f22h(s0 * il, s1 * il);
    }
}

// ---------------- launch ----------------
extern "C" void kernel_launch(void* const* d_in, const int* in_sizes, int n_in,
                              void* d_out, int out_size)
{
    const float* v  = (const float*)d_in[0];
    const float* k  = (const float*)d_in[1];
    const float* q  = (const float*)d_in[2];
    const unsigned char* mask = (const unsigned char*)d_in[3];
    const float* Wv = (const float*)d_in[4];
    const float* bv = (const float*)d_in[5];
    const float* Wk = (const float*)d_in[6];
    const float* bk = (const float*)d_in[7];
    const float* Wq = (const float*)d_in[8];
    const float* bq = (const float*)d_in[9];
    const float* Wt = (const float*)d_in[10];
    const float* bt = (const float*)d_in[11];
    const float* Wm = (const float*)d_in[12];
    const float* bm = (const float*)d_in[13];
    float* out = (float*)d_out;

    __half *qh, *kh, *vh, *Wqh, *Wkh, *Wvh, *Wmh, *qp, *kp, *vp, *atted;
    float *thr, *colsum;
    cudaGetSymbolAddress((void**)&qh,  g_qh);
    cudaGetSymbolAddress((void**)&kh,  g_kh);
    cudaGetSymbolAddress((void**)&vh,  g_vh);
    cudaGetSymbolAddress((void**)&Wqh, g_Wqh);
    cudaGetSymbolAddress((void**)&Wkh, g_Wkh);
    cudaGetSymbolAddress((void**)&Wvh, g_Wvh);
    cudaGetSymbolAddress((void**)&Wmh, g_Wmh);
    cudaGetSymbolAddress((void**)&qp,  g_qp);
    cudaGetSymbolAddress((void**)&kp,  g_kp);
    cudaGetSymbolAddress((void**)&vp,  g_vp);
    cudaGetSymbolAddress((void**)&atted, g_atted);
    cudaGetSymbolAddress((void**)&thr,   g_thr);
    cudaGetSymbolAddress((void**)&colsum, g_colsum);

    cudaFuncSetAttribute(attn_kernel, cudaFuncAttributeMaxDynamicSharedMemorySize, ATTN_SMEM);
    cudaFuncSetAttribute(gemm_f16_kernel<__half, false>, cudaFuncAttributeMaxDynamicSharedMemorySize, GEMM_SMEM);
    cudaFuncSetAttribute(gemm_f16_kernel<float, true>,   cudaFuncAttributeMaxDynamicSharedMemorySize, GEMM_SMEM);

    cvt_all<<<8192, 256>>>(Wq, Wk, Wv, Wm, q, k, v, Wqh, Wkh, Wvh, Wmh, qh, kh, vh);

    gemm_f16_kernel<__half, false><<<dim3(8, 32, 3), 512, GEMM_SMEM>>>(
        qh, kh, vh, Wqh, Wkh, Wvh, bq, bk, bv, qp, kp, vp, nullptr, nullptr);

    threshold_kernel<<<GM, 128>>>(qp, kp, Wt, bt, thr, colsum);

    attn_kernel<<<Bb * NHh * (Ll / QT), 512, ATTN_SMEM>>>(qp, kp, vp, mask, atted, colsum);

    gemm_f16_kernel<float, true><<<dim3(8, 32, 1), 512, GEMM_SMEM>>>(
        atted, atted, atted, Wmh, Wmh, Wmh, bm, bm, bm, out, out, out, colsum, thr);
}

// round 10
// speedup vs baseline: 1.1319x; 1.1319x over previous
#include <cuda_runtime.h>
#include <cuda_fp16.h>

// Problem constants
constexpr int Bb  = 2;
constexpr int Ll  = 2048;
constexpr int Hh  = 1024;
constexpr int NHh = 16;
constexpr int DHd = 64;

constexpr int GM = Bb * Ll;   // 4096
constexpr int GN = Hh;        // 1024
constexpr int GK = Hh;        // 1024

// ---------------- device scratch ----------------
__device__ __half g_qh[GM * Hh];
__device__ __half g_kh[GM * Hh];
__device__ __half g_vh[GM * Hh];
__device__ __half g_Wqh[Hh * Hh];
__device__ __half g_Wkh[Hh * Hh];
__device__ __half g_Wvh[Hh * Hh];
__device__ __half g_Wmh[Hh * Hh];
__device__ __half g_qp[GM * Hh];
__device__ __half g_kp[GM * Hh];
__device__ __half g_vp[GM * Hh];
__device__ __half g_atted[GM * Hh];
__device__ float  g_thr[GM];
__device__ float  g_colsum[GM];

// ---------------- helpers ----------------
__device__ __forceinline__ unsigned f22h(float a, float b) {
    __half2 h = __floats2half2_rn(a, b);
    return *(unsigned*)&h;
}

__device__ __forceinline__ unsigned smem_u32(const void* p) {
    unsigned a;
    asm("{ .reg .u64 t; cvta.to.shared.u64 t, %1; cvt.u32.u64 %0, t; }" : "=r"(a) : "l"(p));
    return a;
}

__device__ __forceinline__ void cp16(unsigned dst, const void* src) {
    asm volatile("cp.async.cg.shared.global [%0], [%1], 16;" :: "r"(dst), "l"(src));
}
#define CP_COMMIT() asm volatile("cp.async.commit_group;")
#define CP_WAIT(n)  asm volatile("cp.async.wait_group %0;" :: "n"(n))

__device__ __forceinline__ void ldsm_x4(unsigned& r0, unsigned& r1, unsigned& r2, unsigned& r3, unsigned addr) {
    asm volatile("ldmatrix.sync.aligned.m8n8.x4.shared.b16 {%0,%1,%2,%3}, [%4];"
                 : "=r"(r0), "=r"(r1), "=r"(r2), "=r"(r3) : "r"(addr));
}
__device__ __forceinline__ void ldsm_x4t(unsigned& r0, unsigned& r1, unsigned& r2, unsigned& r3, unsigned addr) {
    asm volatile("ldmatrix.sync.aligned.m8n8.x4.trans.shared.b16 {%0,%1,%2,%3}, [%4];"
                 : "=r"(r0), "=r"(r1), "=r"(r2), "=r"(r3) : "r"(addr));
}

__device__ __forceinline__ void mma_f16(
    float& c0, float& c1, float& c2, float& c3,
    unsigned a0, unsigned a1, unsigned a2, unsigned a3,
    unsigned b0, unsigned b1)
{
    asm volatile(
        "mma.sync.aligned.m16n8k16.row.col.f32.f16.f16.f32 "
        "{%0,%1,%2,%3},{%4,%5,%6,%7},{%8,%9},{%0,%1,%2,%3};"
        : "+f"(c0), "+f"(c1), "+f"(c2), "+f"(c3)
        : "r"(a0), "r"(a1), "r"(a2), "r"(a3), "r"(b0), "r"(b1));
}

__device__ __forceinline__ unsigned f2key(float f) {
    unsigned b = __float_as_uint(f);
    return (b & 0x80000000u) ? ~b : (b | 0x80000000u);
}
__device__ __forceinline__ float key2f(unsigned u) {
    return __uint_as_float((u & 0x80000000u) ? (u & 0x7fffffffu) : ~u);
}

// ---------------- converter: fp32 -> fp16 for all GEMM operands ----------------
__global__ void __launch_bounds__(256) cvt_all(
    const float* __restrict__ Wq, const float* __restrict__ Wk,
    const float* __restrict__ Wv, const float* __restrict__ Wm,
    const float* __restrict__ q,  const float* __restrict__ k,
    const float* __restrict__ v,
    __half* Wqh, __half* Wkh, __half* Wvh, __half* Wmh,
    __half* qh, __half* kh, __half* vh)
{
    int bid = blockIdx.x;
    const float* src; __half* dst; int off;
    if      (bid < 512)  { src = Wq; dst = Wqh; off = bid; }
    else if (bid < 1024) { src = Wk; dst = Wkh; off = bid - 512; }
    else if (bid < 1536) { src = Wv; dst = Wvh; off = bid - 1024; }
    else if (bid < 2048) { src = Wm; dst = Wmh; off = bid - 1536; }
    else if (bid < 4096) { src = q;  dst = qh;  off = bid - 2048; }
    else if (bid < 6144) { src = k;  dst = kh;  off = bid - 4096; }
    else                 { src = v;  dst = vh;  off = bid - 6144; }
    size_t base = (size_t)off * 2048 + threadIdx.x * 8;
    float4 f0 = *(const float4*)&src[base];
    float4 f1 = *(const float4*)&src[base + 4];
    uint4 o = { f22h(f0.x, f0.y), f22h(f0.z, f0.w), f22h(f1.x, f1.y), f22h(f1.z, f1.w) };
    *(uint4*)&dst[base] = o;
}

// ---------------- fp16 GEMM v3 (R8 winner, unchanged) ----------------
constexpr int G_ASTH = 40;
constexpr int G_BSTH = 136;
constexpr int G_ASB  = 128 * G_ASTH * 2;
constexpr int G_BSB  = 32 * G_BSTH * 2;
constexpr int G_STAGE = G_ASB + G_BSB;
constexpr int GEMM_SMEM = 3 * G_STAGE;

template <typename TC, bool GATED>
__global__ void __launch_bounds__(512, 2) gemm_f16_kernel(
    const __half* __restrict__ A0, const __half* __restrict__ A1, const __half* __restrict__ A2,
    const __half* __restrict__ W0, const __half* __restrict__ W1, const __half* __restrict__ W2,
    const float* __restrict__ b0p, const float* __restrict__ b1p, const float* __restrict__ b2p,
    TC* __restrict__ C0, TC* __restrict__ C1, TC* __restrict__ C2,
    const float* __restrict__ colsum, const float* __restrict__ thr)
{
    extern __shared__ __align__(16) char smb[];
    const unsigned sb = smem_u32(smb);

    const int z = blockIdx.z;
    const __half* A = (z == 0) ? A0 : (z == 1) ? A1 : A2;
    const __half* W = (z == 0) ? W0 : (z == 1) ? W1 : W2;
    const float* bias = (z == 0) ? b0p : (z == 1) ? b1p : b2p;
    TC* C = (z == 0) ? C0 : (z == 1) ? C1 : C2;

    const int t    = threadIdx.x;
    const int w    = t >> 5;
    const int lane = t & 31;
    const int g    = lane >> 2;
    const int tg   = lane & 3;
    const int wm   = (w & 3) * 32;
    const int wn   = (w >> 2) * 32;

    const int m0 = blockIdx.y * 128;
    const int n0 = blockIdx.x * 128;

    const int arow = (lane & 7) + ((lane >> 3) & 1) * 8;
    const int acol = (lane >> 4) * 8;

    const int a_row = t >> 2;
    const int a_seg = (t & 3) * 8;
    const int w_row = t >> 4;
    const int w_seg = (t & 15) * 8;

    auto stage = [&](int s, int kt) {
        const int k0 = kt * 32;
        unsigned as = sb + s * G_STAGE;
        unsigned bs = as + G_ASB;
        cp16(as + (a_row * G_ASTH + a_seg) * 2, &A[(size_t)(m0 + a_row) * GK + k0 + a_seg]);
        cp16(bs + (w_row * G_BSTH + w_seg) * 2, &W[(size_t)(k0 + w_row) * GN + n0 + w_seg]);
    };

    constexpr int NT = GK / 32;
    stage(0, 0); CP_COMMIT();
    stage(1, 1); CP_COMMIT();

    float c[2][4][4] = {};

    for (int kt = 0; kt < NT; kt++) {
        CP_WAIT(1);
        __syncthreads();
        if (kt + 2 < NT) stage((kt + 2) % 3, kt + 2);
        CP_COMMIT();

        const unsigned as = sb + (kt % 3) * G_STAGE;
        const unsigned bs = as + G_ASB;

        #pragma unroll
        for (int kb = 0; kb < 2; kb++) {
            unsigned a[2][4];
            #pragma unroll
            for (int mt = 0; mt < 2; mt++)
                ldsm_x4(a[mt][0], a[mt][1], a[mt][2], a[mt][3],
                        as + ((wm + mt * 16 + arow) * G_ASTH + kb * 16 + acol) * 2);
            unsigned bf[2][4];
            #pragma unroll
            for (int nn = 0; nn < 2; nn++)
                ldsm_x4t(bf[nn][0], bf[nn][1], bf[nn][2], bf[nn][3],
                         bs + ((kb * 16 + arow) * G_BSTH + wn + nn * 16 + acol) * 2);
            #pragma unroll
            for (int mt = 0; mt < 2; mt++)
                #pragma unroll
                for (int ng = 0; ng < 4; ng++)
                    mma_f16(c[mt][ng][0], c[mt][ng][1], c[mt][ng][2], c[mt][ng][3],
                            a[mt][0], a[mt][1], a[mt][2], a[mt][3],
                            bf[ng >> 1][(ng & 1) * 2], bf[ng >> 1][(ng & 1) * 2 + 1]);
        }
        __syncthreads();
    }

    #pragma unroll
    for (int mt = 0; mt < 2; mt++) {
        const int r = m0 + wm + mt * 16 + g;
        float gv0 = 1.f, gv1 = 1.f;
        if (GATED) {
            gv0 = ((colsum[r]     - thr[r])     > 0.f) ? 1.f : 0.f;
            gv1 = ((colsum[r + 8] - thr[r + 8]) > 0.f) ? 1.f : 0.f;
        }
        #pragma unroll
        for (int ng = 0; ng < 4; ng++) {
            const int col = n0 + wn + ng * 8 + 2 * tg;
            float2 bb = *(const float2*)&bias[col];
            float o00 = c[mt][ng][0] * gv0 + bb.x;
            float o01 = c[mt][ng][1] * gv0 + bb.y;
            float o10 = c[mt][ng][2] * gv1 + bb.x;
            float o11 = c[mt][ng][3] * gv1 + bb.y;
            if constexpr (sizeof(TC) == 2) {
                *(unsigned*)&C[(size_t)r * GN + col]       = f22h(o00, o01);
                *(unsigned*)&C[(size_t)(r + 8) * GN + col] = f22h(o10, o11);
            } else {
                *(float2*)&C[(size_t)r * GN + col]       = make_float2(o00, o01);
                *(float2*)&C[(size_t)(r + 8) * GN + col] = make_float2(o10, o11);
            }
        }
    }
}

// ---------------- threshold (also zeroes colsum) ----------------
__global__ void __launch_bounds__(128) threshold_kernel(
    const __half* __restrict__ qp, const __half* __restrict__ kp,
    const float* __restrict__ Wt, const float* __restrict__ bt,
    float* __restrict__ thr, float* __restrict__ colsum)
{
    __shared__ float red[4];
    const int row = blockIdx.x;
    const int t = threadIdx.x;
    const __half* qr = qp + (size_t)row * Hh;
    const __half* kr = kp + (size_t)row * Hh;
    float acc = 0.f;
    for (int i = t; i < Hh; i += 128)
        acc += __half2float(qr[i]) * __half2float(kr[i]) * Wt[i];
    #pragma unroll
    for (int o = 16; o; o >>= 1) acc += __shfl_xor_sync(0xffffffffu, acc, o);
    if ((t & 31) == 0) red[t >> 5] = acc;
    __syncthreads();
    if (t == 0) {
        thr[row] = red[0] + red[1] + red[2] + red[3] + bt[0];
        colsum[row] = 0.f;
    }
}

// ---------------- attention: QT=32 (R8 base), fewer syncs, mma colsum ----------------
constexpr int QT  = 32;
constexpr int KT  = 128;
constexpr int NKT = Ll / KT;        // 16

constexpr int SSTH  = 2056;
constexpr int QSTH  = 72;
constexpr int KVSTH = 72;
constexpr int KVBUF = KT * KVSTH;

constexpr int QH_OFF = QT * SSTH;
constexpr int KV_OFF = QH_OFF + QT * QSTH;
constexpr int FL_OFF = KV_OFF + 3 * KVBUF;
constexpr int ATTN_SMEM = FL_OFF * 2 + 64 * 4;

constexpr int RROW = 68;
constexpr int RSLAB = 32 * RROW;

__global__ void __launch_bounds__(512, 1) attn_kernel(
    const __half* __restrict__ qp, const __half* __restrict__ kp,
    const __half* __restrict__ vp, const unsigned char* __restrict__ mask,
    __half* __restrict__ atted, float* __restrict__ colsum)
{
    extern __shared__ __align__(16) char smb[];
    __half* Sh = (__half*)smb;
    __half* Qh = (__half*)smb + QH_OFF;
    unsigned* rowmaxU = (unsigned*)(smb + FL_OFF * 2);
    float* invl = (float*)(smb + FL_OFF * 2 + 128);
    const unsigned sb   = smem_u32(smb);
    const unsigned shS  = sb;
    const unsigned shQ  = sb + QH_OFF * 2;
    const unsigned shKV = sb + KV_OFF * 2;

    const int t    = threadIdx.x;
    const int w    = t >> 5;
    const int lane = t & 31;
    const int g    = lane >> 2;
    const int tg   = lane & 3;

    const int bx = blockIdx.x;
    const int qt = bx & 63;
    const int h  = (bx >> 6) & 15;
    const int b  = bx >> 10;
    const int q0 = qt * QT;
    const int hd = h * DHd;

    const int arow = (lane & 7) + ((lane >> 3) & 1) * 8;
    const int acol = (lane >> 4) * 8;
    const int brow = lane & 7;
    const int bseg = (lane >> 3) * 8;

    const __half* kbase = kp + (size_t)(b * Ll) * Hh + hd;
    const __half* vbase = vp + (size_t)(b * Ll) * Hh + hd;

    const int s_row0 = t >> 3;
    const int s_c8   = (t & 7) * 8;

    auto stage_tile = [&](int s, const __half* base, int tile) {
        const __half* src = base + (size_t)(tile * KT) * Hh;
        unsigned dst = shKV + s * (KVBUF * 2);
        cp16(dst + (s_row0 * KVSTH + s_c8) * 2,        &src[(size_t)s_row0 * Hh + s_c8]);
        cp16(dst + ((s_row0 + 64) * KVSTH + s_c8) * 2, &src[(size_t)(s_row0 + 64) * Hh + s_c8]);
    };

    if (t < 32) rowmaxU[t] = 0u;
    if (t < 256) {
        int r = t >> 3, c8 = (t & 7) * 8;
        *(uint4*)&Qh[r * QSTH + c8] =
            *(const uint4*)&qp[(size_t)(b * Ll + q0 + r) * Hh + hd + c8];
    }
    stage_tile(0, kbase, 0); CP_COMMIT();
    stage_tile(1, kbase, 1); CP_COMMIT();
    __syncthreads();

    unsigned aq[2][4][4];
    #pragma unroll
    for (int mt = 0; mt < 2; mt++)
        #pragma unroll
        for (int kb = 0; kb < 4; kb++)
            ldsm_x4(aq[mt][kb][0], aq[mt][kb][1], aq[mt][kb][2], aq[mt][kb][3],
                    shQ + ((mt * 16 + arow) * QSTH + kb * 16 + acol) * 2);

    const int n0 = (w & 7) * 8 + (w >> 3) * 64;

    float lm[4] = { -1e30f, -1e30f, -1e30f, -1e30f };

    // ---- QK: one sync per iteration (3-stage pipeline makes trailing sync redundant) ----
    for (int kt = 0; kt < NKT; kt++) {
        CP_WAIT(1);
        __syncthreads();
        if (kt + 2 < NKT) stage_tile((kt + 2) % 3, kbase, kt + 2);
        CP_COMMIT();

        const unsigned kvb = shKV + (kt % 3) * (KVBUF * 2);
        unsigned bk[4][2];
        {
            unsigned r0, r1, r2, r3;
            ldsm_x4(r0, r1, r2, r3, kvb + ((n0 + brow) * KVSTH + bseg) * 2);
            bk[0][0] = r0; bk[0][1] = r1; bk[1][0] = r2; bk[1][1] = r3;
            ldsm_x4(r0, r1, r2, r3, kvb + ((n0 + brow) * KVSTH + 32 + bseg) * 2);
            bk[2][0] = r0; bk[2][1] = r1; bk[3][0] = r2; bk[3][1] = r3;
        }

        float c[2][4] = {};
        #pragma unroll
        for (int mt = 0; mt < 2; mt++)
            #pragma unroll
            for (int kb = 0; kb < 4; kb++)
                mma_f16(c[mt][0], c[mt][1], c[mt][2], c[mt][3],
                        aq[mt][kb][0], aq[mt][kb][1], aq[mt][kb][2], aq[mt][kb][3],
                        bk[kb][0], bk[kb][1]);

        const int key = kt * KT + n0 + 2 * tg;
        const unsigned char m0 = mask[b * Ll + key];
        const unsigned char m1 = mask[b * Ll + key + 1];
        #pragma unroll
        for (int mt = 0; mt < 2; mt++) {
            float s00 = m0 ? -1e9f : c[mt][0] * 0.125f;
            float s01 = m1 ? -1e9f : c[mt][1] * 0.125f;
            float s10 = m0 ? -1e9f : c[mt][2] * 0.125f;
            float s11 = m1 ? -1e9f : c[mt][3] * 0.125f;
            lm[mt * 2]     = fmaxf(lm[mt * 2],     fmaxf(s00, s01));
            lm[mt * 2 + 1] = fmaxf(lm[mt * 2 + 1], fmaxf(s10, s11));
            *(unsigned*)&Sh[(mt * 16 + g)     * SSTH + key] = f22h(s00, s01);
            *(unsigned*)&Sh[(mt * 16 + g + 8) * SSTH + key] = f22h(s10, s11);
        }
    }

    #pragma unroll
    for (int i = 0; i < 4; i++) {
        lm[i] = fmaxf(lm[i], __shfl_xor_sync(0xffffffffu, lm[i], 1));
        lm[i] = fmaxf(lm[i], __shfl_xor_sync(0xffffffffu, lm[i], 2));
    }
    if (tg == 0) {
        atomicMax(&rowmaxU[g],      f2key(lm[0]));
        atomicMax(&rowmaxU[g + 8],  f2key(lm[1]));
        atomicMax(&rowmaxU[g + 16], f2key(lm[2]));
        atomicMax(&rowmaxU[g + 24], f2key(lm[3]));
    }
    __syncthreads();

    // prologue V tiles (overlap with exp/colsum)
    stage_tile(0, vbase, 0); CP_COMMIT();
    stage_tile(1, vbase, 1); CP_COMMIT();

    // ---- exp in place (half), row sums: warp w owns rows 2w, 2w+1 ----
    #pragma unroll
    for (int rr = 0; rr < 2; rr++) {
        const int r = 2 * w + rr;
        const float m = key2f(rowmaxU[r]);
        __half* Sr = Sh + r * SSTH;
        float sum = 0.f;
        #pragma unroll 4
        for (int i = 0; i < 32; i++) {
            const int cc = i * 64 + 2 * lane;
            __half2 hv = *(__half2*)&Sr[cc];
            float e0 = __expf(__half2float(hv.x) - m);
            float e1 = __expf(__half2float(hv.y) - m);
            sum += e0 + e1;
            *(unsigned*)&Sr[cc] = f22h(e0, e1);
        }
        #pragma unroll
        for (int o = 16; o; o >>= 1) sum += __shfl_xor_sync(0xffffffffu, sum, o);
        if (lane == 0) invl[r] = 1.f / sum;
    }
    __syncthreads();

    // ---- colsum via mma: colsum[key] += sum_q invl[q] * P[q][key] ----
    {
        unsigned ai[2][4];
        #pragma unroll
        for (int ks = 0; ks < 2; ks++) {
            if (g == 0) {
                ai[ks][0] = f22h(invl[ks * 16 + 2 * tg],     invl[ks * 16 + 2 * tg + 1]);
                ai[ks][2] = f22h(invl[ks * 16 + 2 * tg + 8], invl[ks * 16 + 2 * tg + 9]);
            } else { ai[ks][0] = 0u; ai[ks][2] = 0u; }
            ai[ks][1] = 0u; ai[ks][3] = 0u;
        }
        const int kw = w * 128;
        #pragma unroll
        for (int ch = 0; ch < 8; ch++) {
            const int key0 = kw + ch * 16;
            unsigned b0[4], b1[4];
            ldsm_x4t(b0[0], b0[1], b0[2], b0[3], shS + (arow * SSTH + key0 + acol) * 2);
            ldsm_x4t(b1[0], b1[1], b1[2], b1[3], shS + ((16 + arow) * SSTH + key0 + acol) * 2);
            float c0 = 0.f, c1 = 0.f, c2 = 0.f, c3 = 0.f;
            float d0 = 0.f, d1 = 0.f, d2 = 0.f, d3 = 0.f;
            mma_f16(c0, c1, c2, c3, ai[0][0], ai[0][1], ai[0][2], ai[0][3], b0[0], b0[1]);
            mma_f16(c0, c1, c2, c3, ai[1][0], ai[1][1], ai[1][2], ai[1][3], b1[0], b1[1]);
            mma_f16(d0, d1, d2, d3, ai[0][0], ai[0][1], ai[0][2], ai[0][3], b0[2], b0[3]);
            mma_f16(d0, d1, d2, d3, ai[1][0], ai[1][1], ai[1][2], ai[1][3], b1[2], b1[3]);
            if (g == 0) {
                atomicAdd(&colsum[b * Ll + key0 + 2 * tg],         c0);
                atomicAdd(&colsum[b * Ll + key0 + 2 * tg + 1],     c1);
                atomicAdd(&colsum[b * Ll + key0 + 8 + 2 * tg],     d0);
                atomicAdd(&colsum[b * Ll + key0 + 8 + 2 * tg + 1], d1);
            }
        }
    }

    // ---- PV: warp = key-slice (w&7)*16 x d-half (w>>3)*32 ----
    const int sk = (w & 7) * 16;
    const int dh = (w >> 3) * 32;
    float c[2][4][4] = {};

    for (int vt = 0; vt < NKT; vt++) {
        CP_WAIT(1);
        __syncthreads();
        if (vt + 2 < NKT) stage_tile((vt + 2) % 3, vbase, vt + 2);
        CP_COMMIT();

        const unsigned kvb = shKV + (vt % 3) * (KVBUF * 2);

        unsigned ap[2][4];
        #pragma unroll
        for (int mt = 0; mt < 2; mt++)
            ldsm_x4(ap[mt][0], ap[mt][1], ap[mt][2], ap[mt][3],
                    shS + ((mt * 16 + arow) * SSTH + vt * KT + sk + acol) * 2);

        unsigned bv[2][4];
        #pragma unroll
        for (int nn = 0; nn < 2; nn++)
            ldsm_x4t(bv[nn][0], bv[nn][1], bv[nn][2], bv[nn][3],
                     kvb + ((sk + arow) * KVSTH + dh + nn * 16 + acol) * 2);

        #pragma unroll
        for (int mt = 0; mt < 2; mt++)
            #pragma unroll
            for (int ng = 0; ng < 4; ng++)
                mma_f16(c[mt][ng][0], c[mt][ng][1], c[mt][ng][2], c[mt][ng][3],
                        ap[mt][0], ap[mt][1], ap[mt][2], ap[mt][3],
                        bv[ng >> 1][(ng & 1) * 2], bv[ng >> 1][(ng & 1) * 2 + 1]);
    }
    __syncthreads();

    float* R = (float*)smb;
    const int slab = w & 7;
    #pragma unroll
    for (int mt = 0; mt < 2; mt++)
        #pragma unroll
        for (int ng = 0; ng < 4; ng++) {
            const int col = dh + ng * 8 + 2 * tg;
            *(float2*)&R[slab * RSLAB + (mt * 16 + g)     * RROW + col] = make_float2(c[mt][ng][0], c[mt][ng][1]);
            *(float2*)&R[slab * RSLAB + (mt * 16 + g + 8) * RROW + col] = make_float2(c[mt][ng][2], c[mt][ng][3]);
        }
    __syncthreads();

    for (int id = t; id < QT * DHd / 2; id += 512) {
        const int r  = id >> 5;
        const int d  = (id & 31) * 2;
        float s0 = 0.f, s1 = 0.f;
        #pragma unroll
        for (int sl = 0; sl < 8; sl++) {
            s0 += R[sl * RSLAB + r * RROW + d];
            s1 += R[sl * RSLAB + r * RROW + d + 1];
        }
        const float il = invl[r];
        *(unsigned*)&atted[(size_t)(b * Ll + q0 + r) * Hh + hd + d] = f22h(s0 * il, s1 * il);
    }
}

// ---------------- launch ----------------
extern "C" void kernel_launch(void* const* d_in, const int* in_sizes, int n_in,
                              void* d_out, int out_size)
{
    const float* v  = (const float*)d_in[0];
    const float* k  = (const float*)d_in[1];
    const float* q  = (const float*)d_in[2];
    const unsigned char* mask = (const unsigned char*)d_in[3];
    const float* Wv = (const float*)d_in[4];
    const float* bv = (const float*)d_in[5];
    const float* Wk = (const float*)d_in[6];
    const float* bk = (const float*)d_in[7];
    const float* Wq = (const float*)d_in[8];
    const float* bq = (const float*)d_in[9];
    const float* Wt = (const float*)d_in[10];
    const float* bt = (const float*)d_in[11];
    const float* Wm = (const float*)d_in[12];
    const float* bm = (const float*)d_in[13];
    float* out = (float*)d_out;

    __half *qh, *kh, *vh, *Wqh, *Wkh, *Wvh, *Wmh, *qp, *kp, *vp, *atted;
    float *thr, *colsum;
    cudaGetSymbolAddress((void**)&qh,  g_qh);
    cudaGetSymbolAddress((void**)&kh,  g_kh);
    cudaGetSymbolAddress((void**)&vh,  g_vh);
    cudaGetSymbolAddress((void**)&Wqh, g_Wqh);
    cudaGetSymbolAddress((void**)&Wkh, g_Wkh);
    cudaGetSymbolAddress((void**)&Wvh, g_Wvh);
    cudaGetSymbolAddress((void**)&Wmh, g_Wmh);
    cudaGetSymbolAddress((void**)&qp,  g_qp);
    cudaGetSymbolAddress((void**)&kp,  g_kp);
    cudaGetSymbolAddress((void**)&vp,  g_vp);
    cudaGetSymbolAddress((void**)&atted, g_atted);
    cudaGetSymbolAddress((void**)&thr,   g_thr);
    cudaGetSymbolAddress((void**)&colsum, g_colsum);

    cudaFuncSetAttribute(attn_kernel, cudaFuncAttributeMaxDynamicSharedMemorySize, ATTN_SMEM);
    cudaFuncSetAttribute(gemm_f16_kernel<__half, false>, cudaFuncAttributeMaxDynamicSharedMemorySize, GEMM_SMEM);
    cudaFuncSetAttribute(gemm_f16_kernel<float, true>,   cudaFuncAttributeMaxDynamicSharedMemorySize, GEMM_SMEM);

    cvt_all<<<8192, 256>>>(Wq, Wk, Wv, Wm, q, k, v, Wqh, Wkh, Wvh, Wmh, qh, kh, vh);

    gemm_f16_kernel<__half, false><<<dim3(8, 32, 3), 512, GEMM_SMEM>>>(
        qh, kh, vh, Wqh, Wkh, Wvh, bq, bk, bv, qp, kp, vp, nullptr, nullptr);

    threshold_kernel<<<GM, 128>>>(qp, kp, Wt, bt, thr, colsum);

    attn_kernel<<<Bb * NHh * (Ll / QT), 512, ATTN_SMEM>>>(qp, kp, vp, mask, atted, colsum);

    gemm_f16_kernel<float, true><<<dim3(8, 32, 1), 512, GEMM_SMEM>>>(
        atted, atted, atted, Wmh, Wmh, Wmh, bm, bm, bm, out, out, out, colsum, thr);
}